// round 16
// baseline (speedup 1.0000x reference)
#include <cuda_runtime.h>
#include <cuda_fp16.h>
#include <cstdint>

#define NUM_K   2048
#define DIMS    256
#define NROWS   16384
#define Q_ELEMS (16 * 256 * 1024)
#define MARGIN  6e-4f
#define NSC     (-0.001953125f)   /* -2/1024, exact */

// ---- device scratch (static; no allocation allowed) ----
__device__ uint32_t g_cbh[(DIMS / 2) * NUM_K];            // fp16 dim-pairs: [dp][code]
__device__ float    g_c2[NUM_K];
__device__ uint32_t g_prox[(size_t)NROWS * (NUM_K / 2)];  // packed fp16 dots (64MB)
__device__ float    g_rowmin[NROWS];
__device__ float    g_zt[(size_t)NROWS * DIMS];           // transposed z rows (16MB)
__device__ float    g_z2[NROWS];
__device__ int      g_idx[NROWS];
__device__ double   g_partial[4096];

// ---- gemm smem layout (bytes) ----
#define GA_OFF   0          // A dim-pair words: 128dp x 128row = 64KB
#define GB0_OFF  65536      // B chunk: 128dp x 128code = 64KB
#define GB1_OFF  131072
#define GC2_OFF  196608     // 2048 floats
#define GMR_OFF  204800     // rowmin scratch 128x8 floats
#define SMEM_GEMM 208896

// ---- prep_z smem ----
#define RPITCH   260
#define SMEM_PZ  (128 * RPITCH * 4)   // 133120

__device__ __forceinline__ uint32_t smem_u32(const void* p) {
    uint32_t a;
    asm("{ .reg .u64 t; cvta.to.shared.u64 t, %1; cvt.u32.u64 %0, t; }"
        : "=r"(a) : "l"(p));
    return a;
}
#define CP_ASYNC16(dst, src) \
    asm volatile("cp.async.cg.shared.global [%0], [%1], 16;" \
                 :: "r"(dst), "l"(src) : "memory")
#define CP_COMMIT() asm volatile("cp.async.commit_group;" ::: "memory")
#define CP_WAIT(n)  asm volatile("cp.async.wait_group %0;" :: "n"(n) : "memory")

// ============================================================================
// Kernel 1: exact c2 (same chain as passing rounds)
// ============================================================================
__global__ void vq_prep_c(const float* __restrict__ cb) {
    int wp = threadIdx.x >> 5, lane = threadIdx.x & 31;
    int row = blockIdx.x * 8 + wp;
    float s = 0.f;
#pragma unroll
    for (int q = 0; q < 8; ++q) {
        float v = cb[(size_t)row * DIMS + lane + q * 32];
        s = __fadd_rn(s, __fmul_rn(v, v));
    }
#pragma unroll
    for (int o = 16; o > 0; o >>= 1)
        s += __shfl_down_sync(0xffffffffu, s, o);
    if (lane == 0) g_c2[row] = s;
}

// ============================================================================
// Kernel 2: pack codebook: word[dp][code] = (fp16(c[code][2dp]*1024),
//                                           fp16(c[code][2dp+1]*1024))
// ============================================================================
__global__ void vq_pack(const float* __restrict__ cb) {
    __shared__ uint32_t t[32][33];
    int kb = blockIdx.x * 32;     // codes
    int dpb = blockIdx.y * 32;    // dim-pairs
    int tx = threadIdx.x, ty = threadIdx.y;   // 32 x 8
#pragma unroll
    for (int i = ty; i < 32; i += 8) {
        float2 v = *reinterpret_cast<const float2*>(
            cb + (size_t)(kb + i) * DIMS + 2 * (dpb + tx));
        __half2 h = __floats2half2_rn(v.x * 1024.0f, v.y * 1024.0f);
        t[i][tx] = *reinterpret_cast<uint32_t*>(&h);
    }
    __syncthreads();
#pragma unroll
    for (int j = ty; j < 32; j += 8)
        g_cbh[(size_t)(dpb + j) * NUM_K + kb + tx] = t[tx][j];
}

// ============================================================================
// Kernel 3: z transpose (g_zt) + exact z2 (identical serial chain)
// ============================================================================
__global__ void __launch_bounds__(256, 1)
vq_prep_z(const float* __restrict__ z) {
    extern __shared__ char sm[];
    float* Zs = reinterpret_cast<float*>(sm);
    const int tid = threadIdx.x;
    const int n0 = blockIdx.x * 128;
    const float* zb = z + (size_t)(n0 >> 10) * 262144 + (n0 & 1023);

    for (int i = tid; i < 8192; i += 256) {
        int d = i >> 5, r4 = i & 31;
        float4 v = *reinterpret_cast<const float4*>(zb + (size_t)d * 1024 + r4 * 4);
        Zs[(r4 * 4 + 0) * RPITCH + d] = v.x;
        Zs[(r4 * 4 + 1) * RPITCH + d] = v.y;
        Zs[(r4 * 4 + 2) * RPITCH + d] = v.z;
        Zs[(r4 * 4 + 3) * RPITCH + d] = v.w;
    }
    __syncthreads();
    if (tid < 128) {
        float s = 0.f;
#pragma unroll 8
        for (int d = 0; d < DIMS; ++d)
            s = __fadd_rn(s, __fmul_rn(Zs[tid * RPITCH + d], Zs[tid * RPITCH + d]));
        g_z2[n0 + tid] = s;
    }
    for (int i = tid; i < 8192; i += 256) {
        int r = i >> 6, ds = i & 63;
        float4 v = *reinterpret_cast<const float4*>(&Zs[r * RPITCH + ds * 4]);
        *reinterpret_cast<float4*>(g_zt + (size_t)(n0 + r) * 256 + ds * 4) = v;
    }
}

// ============================================================================
// Kernel 4: HFMA2 proxy GEMM (dims-in-halves, splat-free) -> packed dots + min
// 256 threads: tx = tid&7 (16 codes), ty = tid>>3 (4 rows)
// ============================================================================
__global__ void __launch_bounds__(256, 1)
vq_gemm(const float* __restrict__ z)
{
    extern __shared__ char sm[];
    uint32_t* AhW = reinterpret_cast<uint32_t*>(sm + GA_OFF);
    float*    c2s = reinterpret_cast<float*>(sm + GC2_OFF);
    float*    mr  = reinterpret_cast<float*>(sm + GMR_OFF);
    const uint32_t sb = smem_u32(sm);
    const int tid = threadIdx.x, tx = tid & 7, ty = tid >> 3;
    const int n0 = blockIdx.x * 128;
    const float* zb = z + (size_t)(n0 >> 10) * 262144 + (n0 & 1023);

    // prefetch B chunk 0: [dp][code 0..127]
    for (int g = tid; g < 4096; g += 256) {
        int dp = g >> 5, c4 = g & 31;
        CP_ASYNC16(sb + GB0_OFF + (uint32_t)(dp * 512 + c4 * 16),
                   g_cbh + (size_t)dp * NUM_K + c4 * 4);
    }
    CP_COMMIT();

    // A: AhW[dp*128 + row] = (fp16 z[row][2dp], fp16 z[row][2dp+1])
    for (int w = tid; w < 16384; w += 256) {
        int dp = w >> 7, row = w & 127;
        float f0 = zb[(size_t)(2 * dp) * 1024 + row];
        float f1 = zb[(size_t)(2 * dp + 1) * 1024 + row];
        __half2 h = __floats2half2_rn(f0, f1);
        AhW[w] = *reinterpret_cast<uint32_t*>(&h);
    }
    for (int i = tid; i < 2048; i += 256) c2s[i] = g_c2[i];

    const __half2 hz = __floats2half2_rn(0.f, 0.f);
    __half2 acc[4][16];
#pragma unroll
    for (int r = 0; r < 4; ++r)
#pragma unroll
        for (int c = 0; c < 16; ++c) acc[r][c] = hz;
    float minv[4] = {3.4e38f, 3.4e38f, 3.4e38f, 3.4e38f};

    for (int t = 0; t < 16; ++t) {
        if (t < 15) {
            const uint32_t obase = (t & 1) ? GB0_OFF : GB1_OFF;
            const uint32_t* src = g_cbh + (size_t)(t + 1) * 128;
            for (int g = tid; g < 4096; g += 256) {
                int dp = g >> 5, c4 = g & 31;
                CP_ASYNC16(sb + obase + (uint32_t)(dp * 512 + c4 * 16),
                           src + (size_t)dp * NUM_K + c4 * 4);
            }
            CP_COMMIT();
            CP_WAIT(1);
        } else {
            CP_WAIT(0);
        }
        __syncthreads();

        const uint32_t* BW = reinterpret_cast<const uint32_t*>(
            sm + ((t & 1) ? GB1_OFF : GB0_OFF));
#pragma unroll 2
        for (int dp = 0; dp < 128; ++dp) {
            uint4 a4 = *reinterpret_cast<const uint4*>(AhW + dp * 128 + ty * 4);
            const uint32_t* bp = BW + dp * 128 + tx * 16;
            uint4 b0 = *reinterpret_cast<const uint4*>(bp);
            uint4 b1 = *reinterpret_cast<const uint4*>(bp + 4);
            uint4 b2 = *reinterpret_cast<const uint4*>(bp + 8);
            uint4 b3 = *reinterpret_cast<const uint4*>(bp + 12);
            uint32_t av[4] = {a4.x, a4.y, a4.z, a4.w};
            uint32_t bv[16] = {b0.x, b0.y, b0.z, b0.w, b1.x, b1.y, b1.z, b1.w,
                               b2.x, b2.y, b2.z, b2.w, b3.x, b3.y, b3.z, b3.w};
#pragma unroll
            for (int r = 0; r < 4; ++r)
#pragma unroll
                for (int c = 0; c < 16; ++c)
                    acc[r][c] = __hfma2(*reinterpret_cast<__half2*>(&av[r]),
                                        *reinterpret_cast<__half2*>(&bv[c]),
                                        acc[r][c]);
        }

        // chunk epilogue: compress dots to fp16 pairs, dump, fp32 proxy min
#pragma unroll
        for (int r = 0; r < 4; ++r) {
            const int row = ty * 4 + r;
            uint32_t* dst = g_prox + (size_t)(n0 + row) * 1024 + t * 64 + tx * 8;
            uint32_t wv[8];
#pragma unroll
            for (int m = 0; m < 8; ++m) {
                float2 fa = __half22float2(acc[r][2 * m]);
                float2 fb = __half22float2(acc[r][2 * m + 1]);
                __half2 hp = __floats2half2_rn(fa.x + fa.y, fb.x + fb.y);
                wv[m] = *reinterpret_cast<uint32_t*>(&hp);
                float2 f = __half22float2(hp);   // same values selres will see
                const int j2 = t * 128 + tx * 16 + 2 * m;
                float p0 = fmaf(NSC, f.x, c2s[j2]);
                float p1 = fmaf(NSC, f.y, c2s[j2 + 1]);
                minv[r] = fminf(minv[r], fminf(p0, p1));
                acc[r][2 * m] = hz;
                acc[r][2 * m + 1] = hz;
            }
            *reinterpret_cast<uint4*>(dst)     = make_uint4(wv[0], wv[1], wv[2], wv[3]);
            *reinterpret_cast<uint4*>(dst + 4) = make_uint4(wv[4], wv[5], wv[6], wv[7]);
        }
        __syncthreads();
    }

    // cross-thread rowmin reduce
#pragma unroll
    for (int r = 0; r < 4; ++r) mr[(ty * 4 + r) * 8 + tx] = minv[r];
    __syncthreads();
    if (tid < 128) {
        float m = mr[tid * 8];
#pragma unroll
        for (int q = 1; q < 8; ++q) m = fminf(m, mr[tid * 8 + q]);
        g_rowmin[n0 + tid] = m;
    }
}

// ============================================================================
// Kernel 5: fused select + exact rescore — 1 warp/row, MLP-8 row load
// ============================================================================
__global__ void __launch_bounds__(256)
vq_selres(const float* __restrict__ cb) {
    __shared__ float c2s[2048];
    __shared__ int scnt[8];
    __shared__ int scand[8][8];
    const int tid = threadIdx.x, w = tid >> 5, lane = tid & 31;
    const int cg = lane >> 2, sub = lane & 3;
    for (int i = tid; i < 2048; i += 256) c2s[i] = g_c2[i];
    __syncthreads();

    const int n = blockIdx.x * 8 + w;
    const float thr = g_rowmin[n] + MARGIN;
    if (lane == 0) scnt[w] = 0;
    __syncwarp();

    const uint32_t* base = g_prox + (size_t)n * 1024;
    uint4 qv[8];
#pragma unroll
    for (int k = 0; k < 8; ++k)
        qv[k] = *reinterpret_cast<const uint4*>(base + k * 128 + lane * 4);

#pragma unroll
    for (int k = 0; k < 8; ++k) {
        const int wi0 = k * 128 + lane * 4;
        uint32_t ws[4] = {qv[k].x, qv[k].y, qv[k].z, qv[k].w};
#pragma unroll
        for (int m = 0; m < 4; ++m) {
            const int wi = wi0 + m;
            float2 f = __half22float2(*reinterpret_cast<__half2*>(&ws[m]));
            float p0 = fmaf(NSC, f.x, c2s[2 * wi]);
            float p1 = fmaf(NSC, f.y, c2s[2 * wi + 1]);
            if (p0 <= thr) {
                int s = atomicAdd(&scnt[w], 1);
                if (s < 8) scand[w][s] = 2 * wi;
            }
            if (p1 <= thr) {
                int s = atomicAdd(&scnt[w], 1);
                if (s < 8) scand[w][s] = 2 * wi + 1;
            }
        }
    }
    __syncwarp();
    const int cnt = scnt[w];
    const float* zr = g_zt + (size_t)n * 256;
    const float z2v = g_z2[n];

    if (cnt <= 8) {
        const int cand = scand[w][(cg < cnt) ? cg : 0];
        const float* cr = cb + (size_t)cand * 256 + sub * 64;
        const float* zp = zr + sub * 64;
        float s = 0.f;
#pragma unroll
        for (int i = 0; i < 16; ++i) {
            float4 a = *reinterpret_cast<const float4*>(zp + i * 4);
            float4 b = *reinterpret_cast<const float4*>(cr + i * 4);
            s = __fmaf_rn(a.x, b.x, s); s = __fmaf_rn(a.y, b.y, s);
            s = __fmaf_rn(a.z, b.z, s); s = __fmaf_rn(a.w, b.w, s);
        }
        s += __shfl_down_sync(0xffffffffu, s, 2, 4);
        s += __shfl_down_sync(0xffffffffu, s, 1, 4);
        float dist = __fsub_rn(__fadd_rn(z2v, c2s[cand]),
                               __fmul_rn(2.0f, s));
        float bestd = 3.4e38f; int besti = 0x7fffffff;
#pragma unroll
        for (int q = 0; q < 8; ++q) {
            float dq = __shfl_sync(0xffffffffu, dist, q * 4);
            int   iq = __shfl_sync(0xffffffffu, cand, q * 4);
            if (dq < bestd || (dq == bestd && iq < besti)) {
                bestd = dq; besti = iq;
            }
        }
        if (lane == 0) g_idx[n] = besti;
    } else {
        float bestd = 3.4e38f; int besti = 0x7fffffff;
        for (int kk = lane; kk < NUM_K; kk += 32) {
            const float* cr = cb + (size_t)kk * 256;
            float s = 0.f;
#pragma unroll 8
            for (int d = 0; d < DIMS; ++d) s = __fmaf_rn(zr[d], cr[d], s);
            float dist = __fsub_rn(__fadd_rn(z2v, c2s[kk]),
                                   __fmul_rn(2.0f, s));
            if (dist < bestd || (dist == bestd && kk < besti)) {
                bestd = dist; besti = kk;
            }
        }
#pragma unroll
        for (int o = 16; o > 0; o >>= 1) {
            float d2 = __shfl_down_sync(0xffffffffu, bestd, o);
            int   i2 = __shfl_down_sync(0xffffffffu, besti, o);
            if (d2 < bestd || (d2 == bestd && i2 < besti)) {
                bestd = d2; besti = i2;
            }
        }
        if (lane == 0) g_idx[n] = besti;
    }
}

// ============================================================================
// Kernel 6: streaming output q = fl(z + fl(c - z)) + fp64 loss partials
// ============================================================================
__global__ void __launch_bounds__(256)
vq_out(const float* __restrict__ z, const float* __restrict__ cb,
       float* __restrict__ out) {
    __shared__ double sp[8];
    const int tid = threadIdx.x;
    const int gi = blockIdx.x * 256 + tid;
    const int e0 = gi * 4;
    const int b  = e0 >> 18;
    const int d  = (e0 >> 10) & 255;
    const int n  = (b << 10) + (e0 & 1023);

    float4 zv = *reinterpret_cast<const float4*>(z + (size_t)e0);
    int j0 = g_idx[n], j1 = g_idx[n + 1], j2 = g_idx[n + 2], j3 = g_idx[n + 3];
    float c0 = cb[(size_t)j0 * 256 + d];
    float c1 = cb[(size_t)j1 * 256 + d];
    float c2 = cb[(size_t)j2 * 256 + d];
    float c3 = cb[(size_t)j3 * 256 + d];
    float e0f = __fsub_rn(c0, zv.x), e1f = __fsub_rn(c1, zv.y);
    float e2f = __fsub_rn(c2, zv.z), e3f = __fsub_rn(c3, zv.w);
    float4 qv = make_float4(__fadd_rn(zv.x, e0f), __fadd_rn(zv.y, e1f),
                            __fadd_rn(zv.z, e2f), __fadd_rn(zv.w, e3f));
    *reinterpret_cast<float4*>(out + (size_t)e0) = qv;

    double ls = (double)e0f * e0f + (double)e1f * e1f
              + (double)e2f * e2f + (double)e3f * e3f;
#pragma unroll
    for (int o = 16; o > 0; o >>= 1)
        ls += __shfl_down_sync(0xffffffffu, ls, o);
    if ((tid & 31) == 0) sp[tid >> 5] = ls;
    __syncthreads();
    if (tid == 0) {
        double s = 0.0;
#pragma unroll
        for (int q = 0; q < 8; ++q) s += sp[q];
        g_partial[blockIdx.x] = s;
    }
}

// ============================================================================
// Kernel 7: finalize losses (reduce 4096 partials)
// ============================================================================
__global__ void vq_final(float* __restrict__ out, int out_size) {
    __shared__ double sp[8];
    int t = threadIdx.x;   // 256
    double v = 0.0;
    for (int i = t; i < 4096; i += 256) v += g_partial[i];
#pragma unroll
    for (int o = 16; o > 0; o >>= 1)
        v += __shfl_down_sync(0xffffffffu, v, o);
    if ((t & 31) == 0) sp[t >> 5] = v;
    __syncthreads();
    if (t == 0) {
        double s = 0.0;
#pragma unroll
        for (int q = 0; q < 8; ++q) s += sp[q];
        double mse = s / (double)Q_ELEMS;
        if (out_size >= Q_ELEMS + 3) {
            out[Q_ELEMS + 0] = (float)(mse * 1.25);
            out[Q_ELEMS + 1] = (float)mse;
            out[Q_ELEMS + 2] = (float)mse;
        }
    }
}

extern "C" void kernel_launch(void* const* d_in, const int* in_sizes, int n_in,
                              void* d_out, int out_size) {
    (void)in_sizes; (void)n_in;
    const float* z  = (const float*)d_in[0];
    const float* cb = (const float*)d_in[1];
    float* out = (float*)d_out;

    cudaFuncSetAttribute(vq_prep_z, cudaFuncAttributeMaxDynamicSharedMemorySize,
                         SMEM_PZ);
    cudaFuncSetAttribute(vq_gemm, cudaFuncAttributeMaxDynamicSharedMemorySize,
                         SMEM_GEMM);

    vq_prep_c<<<256, 256>>>(cb);
    vq_pack<<<dim3(64, 4), dim3(32, 8)>>>(cb);
    vq_prep_z<<<128, 256, SMEM_PZ>>>(z);
    vq_gemm<<<128, 256, SMEM_GEMM>>>(z);
    vq_selres<<<2048, 256>>>(cb);
    vq_out<<<4096, 256>>>(z, cb, out);
    vq_final<<<1, 256>>>(out, out_size);
}

// round 17
// speedup vs baseline: 1.6389x; 1.6389x over previous
#include <cuda_runtime.h>
#include <cuda_fp16.h>
#include <cstdint>

#define NUM_K   2048
#define DIMS    256
#define NROWS   16384
#define Q_ELEMS (16 * 256 * 1024)
#define MARGIN  6e-4f
#define NSC     (-0.001953125f)   /* -2/1024, exact */

// ---- device scratch (static; no allocation allowed) ----
__device__ uint32_t g_cbh[DIMS * (NUM_K / 2)];            // packed fp16 codebook*1024, [d][1024]
__device__ float    g_c2[NUM_K];
__device__ uint32_t g_prox[(size_t)NROWS * (NUM_K / 2)];  // packed fp16 raw dots (64MB)
__device__ float    g_rowmin[NROWS];
__device__ float    g_zt[(size_t)NROWS * DIMS];           // transposed z rows (16MB)
__device__ float    g_z2[NROWS];
__device__ int      g_idx[NROWS];
__device__ double   g_partial[4096];

// ---- gemm smem layout (bytes) ----
#define GA_OFF   0          // A packed fp16 row-pairs: 256d x 64 words = 64KB
#define GB0_OFF  65536      // B chunk: 256d x 64 words = 64KB
#define GB1_OFF  131072
#define GC2_OFF  196608     // 2048 floats
#define GMR_OFF  204800     // rowmin scratch 128x8 floats
#define SMEM_GEMM 208896

// ---- prep_z smem ----
#define RPITCH   260
#define SMEM_PZ  (128 * RPITCH * 4)   // 133120

__device__ __forceinline__ uint32_t smem_u32(const void* p) {
    uint32_t a;
    asm("{ .reg .u64 t; cvta.to.shared.u64 t, %1; cvt.u32.u64 %0, t; }"
        : "=r"(a) : "l"(p));
    return a;
}
#define CP_ASYNC16(dst, src) \
    asm volatile("cp.async.cg.shared.global [%0], [%1], 16;" \
                 :: "r"(dst), "l"(src) : "memory")
#define CP_COMMIT() asm volatile("cp.async.commit_group;" ::: "memory")
#define CP_WAIT(n)  asm volatile("cp.async.wait_group %0;" :: "n"(n) : "memory")

// ============================================================================
// Kernel 1: exact c2 (same chain as passing rounds)
// ============================================================================
__global__ void vq_prep_c(const float* __restrict__ cb) {
    int wp = threadIdx.x >> 5, lane = threadIdx.x & 31;
    int row = blockIdx.x * 8 + wp;
    float s = 0.f;
#pragma unroll
    for (int q = 0; q < 8; ++q) {
        float v = cb[(size_t)row * DIMS + lane + q * 32];
        s = __fadd_rn(s, __fmul_rn(v, v));
    }
#pragma unroll
    for (int o = 16; o > 0; o >>= 1)
        s += __shfl_down_sync(0xffffffffu, s, o);
    if (lane == 0) g_c2[row] = s;
}

// ============================================================================
// Kernel 2: pack codebook: fp16(c*1024), transposed [d][packed code pair]
// ============================================================================
__global__ void vq_pack(const float* __restrict__ cb) {
    __shared__ float t[32][33];
    int kb = blockIdx.x * 32, db = blockIdx.y * 32;
    int tx = threadIdx.x, ty = threadIdx.y;   // 32 x 8
#pragma unroll
    for (int i = ty; i < 32; i += 8)
        t[i][tx] = cb[(size_t)(kb + i) * DIMS + db + tx] * 1024.0f;
    __syncthreads();
    int tid = ty * 32 + tx;
    for (int w = tid; w < 512; w += 256) {
        int dd = w >> 4, jw = w & 15;
        __half2 h = __floats2half2_rn(t[2 * jw][dd], t[2 * jw + 1][dd]);
        g_cbh[(size_t)(db + dd) * (NUM_K / 2) + (kb >> 1) + jw] =
            *reinterpret_cast<uint32_t*>(&h);
    }
}

// ============================================================================
// Kernel 3: z transpose (g_zt) + exact z2 (identical serial chain)
// ============================================================================
__global__ void __launch_bounds__(256, 1)
vq_prep_z(const float* __restrict__ z) {
    extern __shared__ char sm[];
    float* Zs = reinterpret_cast<float*>(sm);
    const int tid = threadIdx.x;
    const int n0 = blockIdx.x * 128;
    const float* zb = z + (size_t)(n0 >> 10) * 262144 + (n0 & 1023);

    for (int i = tid; i < 8192; i += 256) {
        int d = i >> 5, r4 = i & 31;
        float4 v = *reinterpret_cast<const float4*>(zb + (size_t)d * 1024 + r4 * 4);
        Zs[(r4 * 4 + 0) * RPITCH + d] = v.x;
        Zs[(r4 * 4 + 1) * RPITCH + d] = v.y;
        Zs[(r4 * 4 + 2) * RPITCH + d] = v.z;
        Zs[(r4 * 4 + 3) * RPITCH + d] = v.w;
    }
    __syncthreads();
    if (tid < 128) {
        float s = 0.f;
#pragma unroll 8
        for (int d = 0; d < DIMS; ++d)
            s = __fadd_rn(s, __fmul_rn(Zs[tid * RPITCH + d], Zs[tid * RPITCH + d]));
        g_z2[n0 + tid] = s;
    }
    for (int i = tid; i < 8192; i += 256) {
        int r = i >> 6, ds = i & 63;
        float4 v = *reinterpret_cast<const float4*>(&Zs[r * RPITCH + ds * 4]);
        *reinterpret_cast<float4*>(g_zt + (size_t)(n0 + r) * 256 + ds * 4) = v;
    }
}

// ============================================================================
// Kernel 4: HFMA2 proxy GEMM -> raw packed dots + per-row proxy min
// (R13 mainloop; A-splat via half-lane selectors instead of PRMT)
// 256 threads: tx = tid&7 (16 cols), ty = tid>>3 (4 rows)
// ============================================================================
__global__ void __launch_bounds__(256, 1)
vq_gemm(const float* __restrict__ z)
{
    extern __shared__ char sm[];
    uint32_t* AhW = reinterpret_cast<uint32_t*>(sm + GA_OFF);
    float*    c2s = reinterpret_cast<float*>(sm + GC2_OFF);
    float*    mr  = reinterpret_cast<float*>(sm + GMR_OFF);
    const uint32_t sb = smem_u32(sm);
    const int tid = threadIdx.x, tx = tid & 7, ty = tid >> 3;
    const int n0 = blockIdx.x * 128;
    const float* zb = z + (size_t)(n0 >> 10) * 262144 + (n0 & 1023);

    // prefetch B chunk 0
    for (int g = tid; g < 4096; g += 256) {
        int d = g >> 4, w4 = g & 15;
        CP_ASYNC16(sb + GB0_OFF + (uint32_t)(d * 256 + w4 * 16),
                   g_cbh + (size_t)d * 1024 + w4 * 4);
    }
    CP_COMMIT();

    // A: z rows -> packed fp16 row-pairs Ah[d][rp]
    for (int w = tid; w < 16384; w += 256) {
        int d = w >> 6, rp = w & 63;
        float2 f = *reinterpret_cast<const float2*>(zb + (size_t)d * 1024 + rp * 2);
        __half2 h = __floats2half2_rn(f.x, f.y);
        AhW[w] = *reinterpret_cast<uint32_t*>(&h);
    }
    for (int i = tid; i < 2048; i += 256) c2s[i] = g_c2[i];

    const __half2 hz = __floats2half2_rn(0.f, 0.f);
    __half2 acc[4][8];
#pragma unroll
    for (int r = 0; r < 4; ++r)
#pragma unroll
        for (int c = 0; c < 8; ++c) acc[r][c] = hz;
    float minv[4] = {3.4e38f, 3.4e38f, 3.4e38f, 3.4e38f};

    for (int t = 0; t < 16; ++t) {
        if (t < 15) {
            const uint32_t obase = (t & 1) ? GB0_OFF : GB1_OFF;
            const uint32_t* src = g_cbh + (t + 1) * 64;
            for (int g = tid; g < 4096; g += 256) {
                int d = g >> 4, w4 = g & 15;
                CP_ASYNC16(sb + obase + (uint32_t)(d * 256 + w4 * 16),
                           src + (size_t)d * 1024 + w4 * 4);
            }
            CP_COMMIT();
            CP_WAIT(1);
        } else {
            CP_WAIT(0);
        }
        __syncthreads();

        const uint32_t* BW = reinterpret_cast<const uint32_t*>(
            sm + ((t & 1) ? GB1_OFF : GB0_OFF));
#pragma unroll 8
        for (int dk = 0; dk < 256; ++dk) {
            uint2 aw = *reinterpret_cast<const uint2*>(AhW + dk * 64 + ty * 2);
            __half2 w0 = *reinterpret_cast<__half2*>(&aw.x);
            __half2 w1 = *reinterpret_cast<__half2*>(&aw.y);
            __half2 ad[4];
            ad[0] = __low2half2(w0);  ad[1] = __high2half2(w0);
            ad[2] = __low2half2(w1);  ad[3] = __high2half2(w1);
            uint4 b0 = *reinterpret_cast<const uint4*>(BW + dk * 64 + tx * 8);
            uint4 b1 = *reinterpret_cast<const uint4*>(BW + dk * 64 + tx * 8 + 4);
            uint32_t bw[8] = {b0.x, b0.y, b0.z, b0.w, b1.x, b1.y, b1.z, b1.w};
#pragma unroll
            for (int r = 0; r < 4; ++r)
#pragma unroll
                for (int c = 0; c < 8; ++c)
                    acc[r][c] = __hfma2(ad[r],
                                        *reinterpret_cast<__half2*>(&bw[c]),
                                        acc[r][c]);
        }

        // chunk epilogue: dump raw dots + fp32 proxy min; re-zero acc
#pragma unroll
        for (int r = 0; r < 4; ++r) {
            const int row = ty * 4 + r;
            uint32_t* dst = g_prox + (size_t)(n0 + row) * 1024 + t * 64 + tx * 8;
            uint32_t wv[8];
#pragma unroll
            for (int c = 0; c < 8; ++c) {
                float2 f = __half22float2(acc[r][c]);
                const int j2 = t * 128 + tx * 16 + 2 * c;
                float p0 = fmaf(NSC, f.x, c2s[j2]);
                float p1 = fmaf(NSC, f.y, c2s[j2 + 1]);
                minv[r] = fminf(minv[r], fminf(p0, p1));
                wv[c] = *reinterpret_cast<uint32_t*>(&acc[r][c]);
                acc[r][c] = hz;
            }
            *reinterpret_cast<uint4*>(dst)     = make_uint4(wv[0], wv[1], wv[2], wv[3]);
            *reinterpret_cast<uint4*>(dst + 4) = make_uint4(wv[4], wv[5], wv[6], wv[7]);
        }
        __syncthreads();
    }

    // cross-thread rowmin reduce
#pragma unroll
    for (int r = 0; r < 4; ++r) mr[(ty * 4 + r) * 8 + tx] = minv[r];
    __syncthreads();
    if (tid < 128) {
        float m = mr[tid * 8];
#pragma unroll
        for (int q = 1; q < 8; ++q) m = fminf(m, mr[tid * 8 + q]);
        g_rowmin[n0 + tid] = m;
    }
}

// ============================================================================
// Kernel 5: fused select + exact rescore — 1 warp/row, MLP-8 row load
// ============================================================================
__global__ void __launch_bounds__(256)
vq_selres(const float* __restrict__ cb) {
    __shared__ float c2s[2048];
    __shared__ int scnt[8];
    __shared__ int scand[8][8];
    const int tid = threadIdx.x, w = tid >> 5, lane = tid & 31;
    const int cg = lane >> 2, sub = lane & 3;
    for (int i = tid; i < 2048; i += 256) c2s[i] = g_c2[i];
    __syncthreads();

    const int n = blockIdx.x * 8 + w;
    const float thr = g_rowmin[n] + MARGIN;
    if (lane == 0) scnt[w] = 0;
    __syncwarp();

    const uint32_t* base = g_prox + (size_t)n * 1024;
    uint4 qv[8];
#pragma unroll
    for (int k = 0; k < 8; ++k)
        qv[k] = *reinterpret_cast<const uint4*>(base + k * 128 + lane * 4);

#pragma unroll
    for (int k = 0; k < 8; ++k) {
        const int wi0 = k * 128 + lane * 4;
        uint32_t ws[4] = {qv[k].x, qv[k].y, qv[k].z, qv[k].w};
#pragma unroll
        for (int m = 0; m < 4; ++m) {
            const int wi = wi0 + m;
            float2 f = __half22float2(*reinterpret_cast<__half2*>(&ws[m]));
            float p0 = fmaf(NSC, f.x, c2s[2 * wi]);
            float p1 = fmaf(NSC, f.y, c2s[2 * wi + 1]);
            if (p0 <= thr) {
                int s = atomicAdd(&scnt[w], 1);
                if (s < 8) scand[w][s] = 2 * wi;
            }
            if (p1 <= thr) {
                int s = atomicAdd(&scnt[w], 1);
                if (s < 8) scand[w][s] = 2 * wi + 1;
            }
        }
    }
    __syncwarp();
    const int cnt = scnt[w];
    const float* zr = g_zt + (size_t)n * 256;
    const float z2v = g_z2[n];

    if (cnt <= 8) {
        const int cand = scand[w][(cg < cnt) ? cg : 0];
        const float* cr = cb + (size_t)cand * 256 + sub * 64;
        const float* zp = zr + sub * 64;
        float s = 0.f;
#pragma unroll
        for (int i = 0; i < 16; ++i) {
            float4 a = *reinterpret_cast<const float4*>(zp + i * 4);
            float4 b = *reinterpret_cast<const float4*>(cr + i * 4);
            s = __fmaf_rn(a.x, b.x, s); s = __fmaf_rn(a.y, b.y, s);
            s = __fmaf_rn(a.z, b.z, s); s = __fmaf_rn(a.w, b.w, s);
        }
        s += __shfl_down_sync(0xffffffffu, s, 2, 4);
        s += __shfl_down_sync(0xffffffffu, s, 1, 4);
        float dist = __fsub_rn(__fadd_rn(z2v, c2s[cand]),
                               __fmul_rn(2.0f, s));
        float bestd = 3.4e38f; int besti = 0x7fffffff;
#pragma unroll
        for (int q = 0; q < 8; ++q) {
            float dq = __shfl_sync(0xffffffffu, dist, q * 4);
            int   iq = __shfl_sync(0xffffffffu, cand, q * 4);
            if (dq < bestd || (dq == bestd && iq < besti)) {
                bestd = dq; besti = iq;
            }
        }
        if (lane == 0) g_idx[n] = besti;
    } else {
        float bestd = 3.4e38f; int besti = 0x7fffffff;
        for (int kk = lane; kk < NUM_K; kk += 32) {
            const float* cr = cb + (size_t)kk * 256;
            float s = 0.f;
#pragma unroll 8
            for (int d = 0; d < DIMS; ++d) s = __fmaf_rn(zr[d], cr[d], s);
            float dist = __fsub_rn(__fadd_rn(z2v, c2s[kk]),
                                   __fmul_rn(2.0f, s));
            if (dist < bestd || (dist == bestd && kk < besti)) {
                bestd = dist; besti = kk;
            }
        }
#pragma unroll
        for (int o = 16; o > 0; o >>= 1) {
            float d2 = __shfl_down_sync(0xffffffffu, bestd, o);
            int   i2 = __shfl_down_sync(0xffffffffu, besti, o);
            if (d2 < bestd || (d2 == bestd && i2 < besti)) {
                bestd = d2; besti = i2;
            }
        }
        if (lane == 0) g_idx[n] = besti;
    }
}

// ============================================================================
// Kernel 6: streaming output q = fl(z + fl(c - z)) + fp64 loss partials
// ============================================================================
__global__ void __launch_bounds__(256)
vq_out(const float* __restrict__ z, const float* __restrict__ cb,
       float* __restrict__ out) {
    __shared__ double sp[8];
    const int tid = threadIdx.x;
    const int gi = blockIdx.x * 256 + tid;
    const int e0 = gi * 4;
    const int b  = e0 >> 18;
    const int d  = (e0 >> 10) & 255;
    const int n  = (b << 10) + (e0 & 1023);

    float4 zv = *reinterpret_cast<const float4*>(z + (size_t)e0);
    int j0 = g_idx[n], j1 = g_idx[n + 1], j2 = g_idx[n + 2], j3 = g_idx[n + 3];
    float c0 = cb[(size_t)j0 * 256 + d];
    float c1 = cb[(size_t)j1 * 256 + d];
    float c2 = cb[(size_t)j2 * 256 + d];
    float c3 = cb[(size_t)j3 * 256 + d];
    float e0f = __fsub_rn(c0, zv.x), e1f = __fsub_rn(c1, zv.y);
    float e2f = __fsub_rn(c2, zv.z), e3f = __fsub_rn(c3, zv.w);
    float4 qv = make_float4(__fadd_rn(zv.x, e0f), __fadd_rn(zv.y, e1f),
                            __fadd_rn(zv.z, e2f), __fadd_rn(zv.w, e3f));
    *reinterpret_cast<float4*>(out + (size_t)e0) = qv;

    double ls = (double)e0f * e0f + (double)e1f * e1f
              + (double)e2f * e2f + (double)e3f * e3f;
#pragma unroll
    for (int o = 16; o > 0; o >>= 1)
        ls += __shfl_down_sync(0xffffffffu, ls, o);
    if ((tid & 31) == 0) sp[tid >> 5] = ls;
    __syncthreads();
    if (tid == 0) {
        double s = 0.0;
#pragma unroll
        for (int q = 0; q < 8; ++q) s += sp[q];
        g_partial[blockIdx.x] = s;
    }
}

// ============================================================================
// Kernel 7: finalize losses (reduce 4096 partials)
// ============================================================================
__global__ void vq_final(float* __restrict__ out, int out_size) {
    __shared__ double sp[8];
    int t = threadIdx.x;   // 256
    double v = 0.0;
    for (int i = t; i < 4096; i += 256) v += g_partial[i];
#pragma unroll
    for (int o = 16; o > 0; o >>= 1)
        v += __shfl_down_sync(0xffffffffu, v, o);
    if ((t & 31) == 0) sp[t >> 5] = v;
    __syncthreads();
    if (t == 0) {
        double s = 0.0;
#pragma unroll
        for (int q = 0; q < 8; ++q) s += sp[q];
        double mse = s / (double)Q_ELEMS;
        if (out_size >= Q_ELEMS + 3) {
            out[Q_ELEMS + 0] = (float)(mse * 1.25);
            out[Q_ELEMS + 1] = (float)mse;
            out[Q_ELEMS + 2] = (float)mse;
        }
    }
}

extern "C" void kernel_launch(void* const* d_in, const int* in_sizes, int n_in,
                              void* d_out, int out_size) {
    (void)in_sizes; (void)n_in;
    const float* z  = (const float*)d_in[0];
    const float* cb = (const float*)d_in[1];
    float* out = (float*)d_out;

    cudaFuncSetAttribute(vq_prep_z, cudaFuncAttributeMaxDynamicSharedMemorySize,
                         SMEM_PZ);
    cudaFuncSetAttribute(vq_gemm, cudaFuncAttributeMaxDynamicSharedMemorySize,
                         SMEM_GEMM);

    vq_prep_c<<<256, 256>>>(cb);
    vq_pack<<<dim3(64, 8), dim3(32, 8)>>>(cb);
    vq_prep_z<<<128, 256, SMEM_PZ>>>(z);
    vq_gemm<<<128, 256, SMEM_GEMM>>>(z);
    vq_selres<<<2048, 256>>>(cb);
    vq_out<<<4096, 256>>>(z, cb, out);
    vq_final<<<1, 256>>>(out, out_size);
}